// round 15
// baseline (speedup 1.0000x reference)
#include <cuda_runtime.h>
#include <cuda_bf16.h>
#include <cstdint>
#include <float.h>

#define NB    4096
#define NI    50000
#define NIPAD 50048
#define DIM   256
#define TOPK  10
#define TOPC  16
#define BM    128
#define BN    128
#define BK    32          // bf16 k per smem stage
#define NSTG  (DIM / BK)  // 8 stages
#define LDA   40          // smem row stride (bf16) -> conflict-free frag loads

#define TIE_EPS 1.2e-8

// ---- static device scratch --------------------------------------------------
__device__ __nv_bfloat16 g_itemsB[(size_t)NIPAD * DIM];  // [item][d] bf16, pad=0
__device__ __nv_bfloat16 g_usersB[(size_t)NB * DIM];     // [row][d] bf16 (gathered)
__device__ float g_scores[(size_t)NB * NIPAD];           // masked fp32 scores
__device__ int   g_candI[(size_t)NB * TOPC];
__device__ int   g_maskMode;                             // 0=uint8, 1=int32, 2=float32

// ---- helpers ----------------------------------------------------------------
__device__ __forceinline__ bool better(float v1, int i1, float v2, int i2) {
    return (v1 > v2) || (v1 == v2 && i1 < i2);
}
__device__ __forceinline__ bool beforeD(double va, int ia, double vb, int ib) {
    double d = va - vb;
    if (d > TIE_EPS)  return true;
    if (d < -TIE_EPS) return false;
    return ia < ib;
}
__device__ __forceinline__ void cpasync16(uint32_t s, const void* g) {
    asm volatile("cp.async.cg.shared.global [%0], [%1], 16;" :: "r"(s), "l"(g) : "memory");
}
__device__ __forceinline__ void cp_commit() {
    asm volatile("cp.async.commit_group;" ::: "memory");
}
__device__ __forceinline__ void mma_bf16(float* d, const uint32_t* a, const uint32_t* b) {
    asm volatile(
        "mma.sync.aligned.m16n8k16.row.col.f32.bf16.bf16.f32 "
        "{%0,%1,%2,%3}, {%4,%5,%6,%7}, {%8,%9}, {%0,%1,%2,%3};"
        : "+f"(d[0]), "+f"(d[1]), "+f"(d[2]), "+f"(d[3])
        : "r"(a[0]), "r"(a[1]), "r"(a[2]), "r"(a[3]), "r"(b[0]), "r"(b[1]));
}

// ---- detect mask dtype ------------------------------------------------------
__global__ void kDetectMask(const unsigned char* __restrict__ m) {
    __shared__ int s_nz, s_3f;
    if (threadIdx.x == 0) { s_nz = 0; s_3f = 0; }
    __syncthreads();
    int nz = 0, n3f = 0;
    for (int i = threadIdx.x * 16; i < threadIdx.x * 16 + 16; i++) {
        unsigned char b = m[i];
        if (b) nz++;
        if (b == 0x3F) n3f++;
    }
    atomicAdd(&s_nz, nz);
    atomicAdd(&s_3f, n3f);
    __syncthreads();
    if (threadIdx.x == 0) {
        int mode;
        if (s_3f > 100)        mode = 2;
        else if (s_nz > 1024)  mode = 0;
        else                   mode = 1;
        g_maskMode = mode;
    }
}

// ---- convert items fp32 -> bf16 (row-major, K-contiguous; pad rows = 0) -----
__global__ void kConvItems(const float* __restrict__ src) {
    size_t idx = (size_t)blockIdx.x * blockDim.x + threadIdx.x;   // 8 elems each
    if (idx >= (size_t)NIPAD * DIM / 8) return;
    int row = (int)(idx >> 5);            // DIM/8 = 32 segments per row
    int seg = (int)(idx & 31);
    size_t base = (size_t)row * DIM + seg * 8;
    float4 fa = make_float4(0.f, 0.f, 0.f, 0.f), fb = fa;
    if (row < NI) {
        fa = *reinterpret_cast<const float4*>(src + base);
        fb = *reinterpret_cast<const float4*>(src + base + 4);
    }
    __nv_bfloat162 h0 = __floats2bfloat162_rn(fa.x, fa.y);
    __nv_bfloat162 h1 = __floats2bfloat162_rn(fa.z, fa.w);
    __nv_bfloat162 h2 = __floats2bfloat162_rn(fb.x, fb.y);
    __nv_bfloat162 h3 = __floats2bfloat162_rn(fb.z, fb.w);
    uint4 o;
    o.x = *reinterpret_cast<const unsigned*>(&h0);
    o.y = *reinterpret_cast<const unsigned*>(&h1);
    o.z = *reinterpret_cast<const unsigned*>(&h2);
    o.w = *reinterpret_cast<const unsigned*>(&h3);
    *reinterpret_cast<uint4*>(&g_itemsB[base]) = o;
}

// ---- gather + convert users -> bf16 ----------------------------------------
__global__ void kConvUsers(const float* __restrict__ embu, const int* __restrict__ users) {
    size_t idx = (size_t)blockIdx.x * blockDim.x + threadIdx.x;
    if (idx >= (size_t)NB * DIM / 8) return;
    int row = (int)(idx >> 5);
    int seg = (int)(idx & 31);
    int u = users[row];
    size_t sbase = (size_t)u * DIM + seg * 8;
    float4 fa = *reinterpret_cast<const float4*>(embu + sbase);
    float4 fb = *reinterpret_cast<const float4*>(embu + sbase + 4);
    __nv_bfloat162 h0 = __floats2bfloat162_rn(fa.x, fa.y);
    __nv_bfloat162 h1 = __floats2bfloat162_rn(fa.z, fa.w);
    __nv_bfloat162 h2 = __floats2bfloat162_rn(fb.x, fb.y);
    __nv_bfloat162 h3 = __floats2bfloat162_rn(fb.z, fb.w);
    uint4 o;
    o.x = *reinterpret_cast<const unsigned*>(&h0);
    o.y = *reinterpret_cast<const unsigned*>(&h1);
    o.z = *reinterpret_cast<const unsigned*>(&h2);
    o.w = *reinterpret_cast<const unsigned*>(&h3);
    *reinterpret_cast<uint4*>(&g_usersB[(size_t)row * DIM + seg * 8]) = o;
}

// ---- tensor-core GEMM (bf16 in, fp32 acc) + bias + mask -> g_scores ---------
// block 128x128, 8 warps: warp_m = wid&1 (64 rows), warp_n = wid>>1 (32 cols)
__global__ void __launch_bounds__(256, 2)
kMainTC(const int* __restrict__ users, const float* __restrict__ bias,
        const void* __restrict__ maskRaw) {
    __shared__ __align__(16) __nv_bfloat16 As[2][BM][LDA];
    __shared__ __align__(16) __nv_bfloat16 Bs[2][BN][LDA];
    __shared__ int users_s[BM];

    const int tid  = threadIdx.x;
    const int lane = tid & 31, wid = tid >> 5;
    const int warp_m = wid & 1, warp_n = wid >> 1;
    const int ib = blockIdx.x * BN;
    const int u0 = blockIdx.y * BM;
    const int g  = lane >> 2;          // 0..7
    const int t2 = (lane & 3) * 2;     // 0,2,4,6

    if (tid < BM) users_s[tid] = users[u0 + tid];

    float acc[4][4][4];
#pragma unroll
    for (int im = 0; im < 4; im++)
#pragma unroll
        for (int in = 0; in < 4; in++)
#pragma unroll
            for (int q = 0; q < 4; q++) acc[im][in][q] = 0.f;

    auto issue = [&](int stage) {
        const int k0 = stage * BK;
        const int buf = stage & 1;
#pragma unroll
        for (int s = 0; s < 2; s++) {
            int c = tid + 256 * s;            // 0..511
            int row = c >> 2;                 // 0..127
            int off8 = (c & 3) * 8;           // 0,8,16,24
            cpasync16((uint32_t)__cvta_generic_to_shared(&As[buf][row][off8]),
                      g_usersB + (size_t)(u0 + row) * DIM + k0 + off8);
            cpasync16((uint32_t)__cvta_generic_to_shared(&Bs[buf][row][off8]),
                      g_itemsB + (size_t)(ib + row) * DIM + k0 + off8);
        }
    };

    issue(0);
    cp_commit();

    for (int s = 0; s < NSTG; s++) {
        const int buf = s & 1;
        if (s + 1 < NSTG) { issue(s + 1); cp_commit(); }
        if (s + 1 < NSTG) asm volatile("cp.async.wait_group 1;" ::: "memory");
        else              asm volatile("cp.async.wait_group 0;" ::: "memory");
        __syncthreads();

#pragma unroll
        for (int kk = 0; kk < 2; kk++) {
            const int kb = kk * 16 + t2;
            uint32_t af[4][4], bf[4][2];
#pragma unroll
            for (int im = 0; im < 4; im++) {
                const int r = warp_m * 64 + im * 16 + g;
                af[im][0] = *reinterpret_cast<const uint32_t*>(&As[buf][r][kb]);
                af[im][1] = *reinterpret_cast<const uint32_t*>(&As[buf][r + 8][kb]);
                af[im][2] = *reinterpret_cast<const uint32_t*>(&As[buf][r][kb + 8]);
                af[im][3] = *reinterpret_cast<const uint32_t*>(&As[buf][r + 8][kb + 8]);
            }
#pragma unroll
            for (int in = 0; in < 4; in++) {
                const int n = warp_n * 32 + in * 8 + g;
                bf[in][0] = *reinterpret_cast<const uint32_t*>(&Bs[buf][n][kb]);
                bf[in][1] = *reinterpret_cast<const uint32_t*>(&Bs[buf][n][kb + 8]);
            }
#pragma unroll
            for (int im = 0; im < 4; im++)
#pragma unroll
                for (int in = 0; in < 4; in++)
                    mma_bf16(acc[im][in], af[im], bf[in]);
        }
        __syncthreads();
    }

    // ---- epilogue: bias + mask + store ----
    const int mode = g_maskMode;
    float bias2[4][2];
#pragma unroll
    for (int in = 0; in < 4; in++) {
        int gc = ib + warp_n * 32 + in * 8 + t2;
        if (gc < NI) {
            float2 bq = *reinterpret_cast<const float2*>(bias + gc);
            bias2[in][0] = bq.x; bias2[in][1] = bq.y;
        } else { bias2[in][0] = 0.f; bias2[in][1] = 0.f; }
    }
#pragma unroll
    for (int im = 0; im < 4; im++) {
#pragma unroll
        for (int half = 0; half < 2; half++) {
            const int r = warp_m * 64 + im * 16 + g + half * 8;
            const int u = users_s[r];
            float* drow = g_scores + (size_t)(u0 + r) * NIPAD + ib;
#pragma unroll
            for (int in = 0; in < 4; in++) {
                const int c = warp_n * 32 + in * 8 + t2;
                const int gc = ib + c;
                if (gc >= NI) continue;   // gc even, NI even -> gc+1 < NI too
                float v0 = acc[im][in][half * 2]     + bias2[in][0];
                float v1 = acc[im][in][half * 2 + 1] + bias2[in][1];
                const size_t eoff = (size_t)u * NI + gc;
                bool m0, m1;
                if (mode == 0) {
                    const unsigned char* mp = (const unsigned char*)maskRaw + eoff;
                    m0 = mp[0] != 0; m1 = mp[1] != 0;
                } else if (mode == 1) {
                    const int* mp = (const int*)maskRaw + eoff;
                    m0 = mp[0] != 0; m1 = mp[1] != 0;
                } else {
                    const float* mp = (const float*)maskRaw + eoff;
                    m0 = mp[0] != 0.f; m1 = mp[1] != 0.f;
                }
                if (m0) v0 = -FLT_MAX;
                if (m1) v1 = -FLT_MAX;
                *reinterpret_cast<float2*>(drow + c) = make_float2(v0, v1);
            }
        }
    }
}

// ---- per-row fp32 top-16 candidate SET --------------------------------------
__global__ void __launch_bounds__(256) kCand() {
    __shared__ float sv[256 * TOPC];
    __shared__ int   si[256 * TOPC];
    const int tid = threadIdx.x;
    const size_t base = (size_t)blockIdx.x * NIPAD;

    float lv[TOPC]; int li[TOPC];
#pragma unroll
    for (int j = 0; j < TOPC; j++) { lv[j] = -FLT_MAX; li[j] = 0x7fffffff; }

    for (int i = tid; i < NI; i += 256) {
        float v = g_scores[base + i];
        if (v == -FLT_MAX) continue;
        if (better(v, i, lv[TOPC - 1], li[TOPC - 1])) {
            float cv = v; int ci = i;
#pragma unroll
            for (int q = 0; q < TOPC; q++) {
                if (better(cv, ci, lv[q], li[q])) {
                    float tv = lv[q]; int ti = li[q];
                    lv[q] = cv; li[q] = ci; cv = tv; ci = ti;
                }
            }
        }
    }
#pragma unroll
    for (int j = 0; j < TOPC; j++) { sv[tid * TOPC + j] = lv[j]; si[tid * TOPC + j] = li[j]; }
    __syncthreads();

    for (int s = 128; s > 0; s >>= 1) {
        if (tid < s) {
            float av[TOPC], bv[TOPC], ov[TOPC];
            int   ai[TOPC], bi[TOPC], oi[TOPC];
#pragma unroll
            for (int j = 0; j < TOPC; j++) {
                av[j] = sv[tid * TOPC + j];       ai[j] = si[tid * TOPC + j];
                bv[j] = sv[(tid + s) * TOPC + j]; bi[j] = si[(tid + s) * TOPC + j];
            }
            int pa = 0, pb = 0;
#pragma unroll
            for (int q = 0; q < TOPC; q++) {
                bool takeA;
                if (pa >= TOPC)      takeA = false;
                else if (pb >= TOPC) takeA = true;
                else                 takeA = better(av[pa], ai[pa], bv[pb], bi[pb]);
                if (takeA) { ov[q] = av[pa]; oi[q] = ai[pa]; pa++; }
                else       { ov[q] = bv[pb]; oi[q] = bi[pb]; pb++; }
            }
#pragma unroll
            for (int j = 0; j < TOPC; j++) { sv[tid * TOPC + j] = ov[j]; si[tid * TOPC + j] = oi[j]; }
        }
        __syncthreads();
    }
    if (tid < TOPC) g_candI[(size_t)blockIdx.x * TOPC + tid] = si[tid];
}

// ---- fp64 re-score candidates; near-tie -> lower index ----------------------
__global__ void __launch_bounds__(128) kRescore(
    const int* __restrict__ users, const float* __restrict__ embu,
    const float* __restrict__ embi, const float* __restrict__ bias,
    float* __restrict__ out) {
    const int warp = threadIdx.x >> 5;
    const int lane = threadIdx.x & 31;
    const int row  = blockIdx.x * 4 + warp;
    if (row >= NB) return;
    const int u = users[row];

    double cs[TOPC]; int ci[TOPC];
    for (int j = 0; j < TOPC; j++) {
        int idx = g_candI[(size_t)row * TOPC + j];
        ci[j] = idx;
        double s;
        if (idx < 0 || idx >= NI) {
            s = -1e300;
        } else {
            double part = 0.0;
            const float* urow = embu + (size_t)u * DIM;
            const float* irow = embi + (size_t)idx * DIM;
#pragma unroll
            for (int m = 0; m < DIM / 32; m++) {
                int k = lane + 32 * m;
                part += (double)urow[k] * (double)irow[k];
            }
#pragma unroll
            for (int off = 16; off > 0; off >>= 1)
                part += __shfl_down_sync(0xffffffffu, part, off);
            s = part + (double)bias[idx];
            s = __shfl_sync(0xffffffffu, s, 0);
        }
        cs[j] = s;
    }

    if (lane == 0) {
#pragma unroll
        for (int a = 1; a < TOPC; a++) {
            double v = cs[a]; int id = ci[a];
            int b = a - 1;
            while (b >= 0 && !beforeD(cs[b], ci[b], v, id)) {
                cs[b + 1] = cs[b]; ci[b + 1] = ci[b]; b--;
            }
            cs[b + 1] = v; ci[b + 1] = id;
        }
        for (int t = 0; t < TOPK; t++)
            out[(size_t)row * TOPK + t] = (float)ci[t];
    }
}

// ---- launch -----------------------------------------------------------------
extern "C" void kernel_launch(void* const* d_in, const int* in_sizes, int n_in,
                              void* d_out, int out_size) {
    const int*   users = nullptr;
    const float* embu  = nullptr;
    const float* embi  = nullptr;
    const float* bias  = nullptr;
    const void*  mask  = nullptr;

    for (int i = 0; i < n_in; i++) {
        long long s = in_sizes[i];
        if      (s == 4096LL      || s == 16384LL)      users = (const int*)d_in[i];
        else if (s == 4194304LL   || s == 16777216LL)   embu  = (const float*)d_in[i];
        else if (s == 12800000LL  || s == 51200000LL)   embi  = (const float*)d_in[i];
        else if (s == 50000LL     || s == 200000LL)     bias  = (const float*)d_in[i];
        else if (s == 1LL         || s == 4LL)          { /* k == 10 */ }
        else                                            mask  = d_in[i];
    }
    float* out = (float*)d_out;

    kDetectMask<<<1, 256>>>((const unsigned char*)mask);
    kConvItems<<<(int)(((size_t)NIPAD * DIM / 8 + 255) / 256), 256>>>(embi);
    kConvUsers<<<(int)(((size_t)NB * DIM / 8 + 255) / 256), 256>>>(embu, users);
    kMainTC<<<dim3(NIPAD / BN, NB / BM), 256>>>(users, bias, mask);
    kCand<<<NB, 256>>>();
    kRescore<<<NB / 4, 128>>>(users, embu, embi, bias, out);
}

// round 16
// speedup vs baseline: 1.9130x; 1.9130x over previous
#include <cuda_runtime.h>
#include <cuda_bf16.h>
#include <cstdint>
#include <float.h>

#define NB    4096
#define NI    50000
#define NIPAD 50048
#define DIM   256
#define TOPK  10
#define TOPC  16
#define BM    128
#define BN    128
#define BK    32
#define NSTG  (DIM / BK)
#define LDA   40
#define BPR   (NIPAD / 8)      // 6256 mask-bit bytes per row
#define CAP   4096             // candidate buffer slots per row
#define TILES_S 4              // seed phase tiles (512 items)
#define NTILES  (NIPAD / BN)   // 391

#define TIE_EPS 1.2e-8

// ---- static device scratch --------------------------------------------------
__device__ __nv_bfloat16 g_itemsB[(size_t)NIPAD * DIM];
__device__ __nv_bfloat16 g_usersB[(size_t)NB * DIM];
__device__ unsigned char g_maskBits[(size_t)NB * BPR];   // gathered, bit-packed
__device__ unsigned long long g_candBuf[(size_t)NB * CAP];
__device__ int   g_cnt[NB];
__device__ float g_thresh[NB];
__device__ int   g_candI[(size_t)NB * TOPC];
__device__ int   g_maskMode;

// ---- helpers ----------------------------------------------------------------
__device__ __forceinline__ bool better(float v1, int i1, float v2, int i2) {
    return (v1 > v2) || (v1 == v2 && i1 < i2);
}
__device__ __forceinline__ bool beforeD(double va, int ia, double vb, int ib) {
    double d = va - vb;
    if (d > TIE_EPS)  return true;
    if (d < -TIE_EPS) return false;
    return ia < ib;
}
__device__ __forceinline__ unsigned long long packCand(float v, int idx) {
    return ((unsigned long long)(unsigned)__float_as_int(v) << 32) | (unsigned)idx;
}
__device__ __forceinline__ void unpackCand(unsigned long long e, float& v, int& idx) {
    v = __int_as_float((int)(e >> 32)); idx = (int)(e & 0xffffffffu);
}
__device__ __forceinline__ void cpasync16(uint32_t s, const void* g) {
    asm volatile("cp.async.cg.shared.global [%0], [%1], 16;" :: "r"(s), "l"(g) : "memory");
}
__device__ __forceinline__ void cp_commit() {
    asm volatile("cp.async.commit_group;" ::: "memory");
}
__device__ __forceinline__ void mma_bf16(float* d, const uint32_t* a, const uint32_t* b) {
    asm volatile(
        "mma.sync.aligned.m16n8k16.row.col.f32.bf16.bf16.f32 "
        "{%0,%1,%2,%3}, {%4,%5,%6,%7}, {%8,%9}, {%0,%1,%2,%3};"
        : "+f"(d[0]), "+f"(d[1]), "+f"(d[2]), "+f"(d[3])
        : "r"(a[0]), "r"(a[1]), "r"(a[2]), "r"(a[3]), "r"(b[0]), "r"(b[1]));
}

// ---- detect mask dtype ------------------------------------------------------
__global__ void kDetectMask(const unsigned char* __restrict__ m) {
    __shared__ int s_nz, s_3f;
    if (threadIdx.x == 0) { s_nz = 0; s_3f = 0; }
    __syncthreads();
    int nz = 0, n3f = 0;
    for (int i = threadIdx.x * 16; i < threadIdx.x * 16 + 16; i++) {
        unsigned char b = m[i];
        if (b) nz++;
        if (b == 0x3F) n3f++;
    }
    atomicAdd(&s_nz, nz);
    atomicAdd(&s_3f, n3f);
    __syncthreads();
    if (threadIdx.x == 0) {
        int mode;
        if (s_3f > 100)        mode = 2;
        else if (s_nz > 1024)  mode = 0;
        else                   mode = 1;
        g_maskMode = mode;
    }
}

// ---- init per-call state ----------------------------------------------------
__global__ void kInit() {
    int i = blockIdx.x * blockDim.x + threadIdx.x;
    if (i < NB) { g_cnt[i] = 0; g_thresh[i] = -FLT_MAX; }
}

// ---- convert items fp32 -> bf16 ---------------------------------------------
__global__ void kConvItems(const float* __restrict__ src) {
    size_t idx = (size_t)blockIdx.x * blockDim.x + threadIdx.x;
    if (idx >= (size_t)NIPAD * DIM / 8) return;
    int row = (int)(idx >> 5);
    int seg = (int)(idx & 31);
    size_t base = (size_t)row * DIM + seg * 8;
    float4 fa = make_float4(0.f, 0.f, 0.f, 0.f), fb = fa;
    if (row < NI) {
        fa = *reinterpret_cast<const float4*>(src + base);
        fb = *reinterpret_cast<const float4*>(src + base + 4);
    }
    __nv_bfloat162 h0 = __floats2bfloat162_rn(fa.x, fa.y);
    __nv_bfloat162 h1 = __floats2bfloat162_rn(fa.z, fa.w);
    __nv_bfloat162 h2 = __floats2bfloat162_rn(fb.x, fb.y);
    __nv_bfloat162 h3 = __floats2bfloat162_rn(fb.z, fb.w);
    uint4 o;
    o.x = *reinterpret_cast<const unsigned*>(&h0);
    o.y = *reinterpret_cast<const unsigned*>(&h1);
    o.z = *reinterpret_cast<const unsigned*>(&h2);
    o.w = *reinterpret_cast<const unsigned*>(&h3);
    *reinterpret_cast<uint4*>(&g_itemsB[base]) = o;
}

// ---- gather + convert users -> bf16 -----------------------------------------
__global__ void kConvUsers(const float* __restrict__ embu, const int* __restrict__ users) {
    size_t idx = (size_t)blockIdx.x * blockDim.x + threadIdx.x;
    if (idx >= (size_t)NB * DIM / 8) return;
    int row = (int)(idx >> 5);
    int seg = (int)(idx & 31);
    int u = users[row];
    size_t sbase = (size_t)u * DIM + seg * 8;
    float4 fa = *reinterpret_cast<const float4*>(embu + sbase);
    float4 fb = *reinterpret_cast<const float4*>(embu + sbase + 4);
    __nv_bfloat162 h0 = __floats2bfloat162_rn(fa.x, fa.y);
    __nv_bfloat162 h1 = __floats2bfloat162_rn(fa.z, fa.w);
    __nv_bfloat162 h2 = __floats2bfloat162_rn(fb.x, fb.y);
    __nv_bfloat162 h3 = __floats2bfloat162_rn(fb.z, fb.w);
    uint4 o;
    o.x = *reinterpret_cast<const unsigned*>(&h0);
    o.y = *reinterpret_cast<const unsigned*>(&h1);
    o.z = *reinterpret_cast<const unsigned*>(&h2);
    o.w = *reinterpret_cast<const unsigned*>(&h3);
    *reinterpret_cast<uint4*>(&g_usersB[(size_t)row * DIM + seg * 8]) = o;
}

// ---- gather + bit-pack mask rows: g_maskBits[row][col/8] --------------------
__global__ void __launch_bounds__(256) kPackMask(const int* __restrict__ users,
                                                 const void* __restrict__ maskRaw) {
    const int row = blockIdx.x;
    const int u = users[row];
    const int mode = g_maskMode;
    unsigned char* dst = g_maskBits + (size_t)row * BPR;

    for (int g16 = threadIdx.x; g16 < NI / 16; g16 += 256) {   // 3125 groups of 16 cols
        unsigned bits = 0;
        if (mode == 0) {
            // u*NI is 16B aligned (50000 % 16 == 0)
            uint4 m = *((const uint4*)((const unsigned char*)maskRaw + (size_t)u * NI) + g16);
            unsigned w[4] = {m.x, m.y, m.z, m.w};
#pragma unroll
            for (int q = 0; q < 4; q++)
#pragma unroll
                for (int b = 0; b < 4; b++)
                    bits |= (((w[q] >> (8 * b)) & 0xffu) ? 1u : 0u) << (q * 4 + b);
        } else if (mode == 1) {
            const int* p = (const int*)maskRaw + (size_t)u * NI + g16 * 16;
#pragma unroll
            for (int j = 0; j < 16; j++) bits |= (p[j] != 0 ? 1u : 0u) << j;
        } else {
            const float* p = (const float*)maskRaw + (size_t)u * NI + g16 * 16;
#pragma unroll
            for (int j = 0; j < 16; j++) bits |= (p[j] != 0.f ? 1u : 0u) << j;
        }
        dst[g16 * 2]     = (unsigned char)(bits & 0xff);
        dst[g16 * 2 + 1] = (unsigned char)(bits >> 8);
    }
    if (threadIdx.x < BPR - NI / 8)                 // pad cols 50000..50047 -> masked
        dst[NI / 8 + threadIdx.x] = 0xFF;
}

// ---- tensor-core GEMM + bias + mask + threshold-append ----------------------
__global__ void __launch_bounds__(256, 2)
kMainTC(const float* __restrict__ bias, int tile0) {
    __shared__ __align__(16) __nv_bfloat16 As[2][BM][LDA];
    __shared__ __align__(16) __nv_bfloat16 Bs[2][BN][LDA];
    __shared__ float th_s[BM];

    const int tid  = threadIdx.x;
    const int lane = tid & 31, wid = tid >> 5;
    const int warp_m = wid & 1, warp_n = wid >> 1;
    const int ib = (tile0 + blockIdx.x) * BN;
    const int u0 = blockIdx.y * BM;
    const int g  = lane >> 2;
    const int t2 = (lane & 3) * 2;

    if (tid < BM) th_s[tid] = g_thresh[u0 + tid];

    float acc[4][4][4];
#pragma unroll
    for (int im = 0; im < 4; im++)
#pragma unroll
        for (int in = 0; in < 4; in++)
#pragma unroll
            for (int q = 0; q < 4; q++) acc[im][in][q] = 0.f;

    auto issue = [&](int stage) {
        const int k0 = stage * BK;
        const int buf = stage & 1;
#pragma unroll
        for (int s = 0; s < 2; s++) {
            int c = tid + 256 * s;
            int row = c >> 2;
            int off8 = (c & 3) * 8;
            cpasync16((uint32_t)__cvta_generic_to_shared(&As[buf][row][off8]),
                      g_usersB + (size_t)(u0 + row) * DIM + k0 + off8);
            cpasync16((uint32_t)__cvta_generic_to_shared(&Bs[buf][row][off8]),
                      g_itemsB + (size_t)(ib + row) * DIM + k0 + off8);
        }
    };

    issue(0);
    cp_commit();

    for (int s = 0; s < NSTG; s++) {
        const int buf = s & 1;
        if (s + 1 < NSTG) { issue(s + 1); cp_commit(); }
        if (s + 1 < NSTG) asm volatile("cp.async.wait_group 1;" ::: "memory");
        else              asm volatile("cp.async.wait_group 0;" ::: "memory");
        __syncthreads();

#pragma unroll
        for (int kk = 0; kk < 2; kk++) {
            const int kb = kk * 16 + t2;
            uint32_t af[4][4], bf[4][2];
#pragma unroll
            for (int im = 0; im < 4; im++) {
                const int r = warp_m * 64 + im * 16 + g;
                af[im][0] = *reinterpret_cast<const uint32_t*>(&As[buf][r][kb]);
                af[im][1] = *reinterpret_cast<const uint32_t*>(&As[buf][r + 8][kb]);
                af[im][2] = *reinterpret_cast<const uint32_t*>(&As[buf][r][kb + 8]);
                af[im][3] = *reinterpret_cast<const uint32_t*>(&As[buf][r + 8][kb + 8]);
            }
#pragma unroll
            for (int in = 0; in < 4; in++) {
                const int n = warp_n * 32 + in * 8 + g;
                bf[in][0] = *reinterpret_cast<const uint32_t*>(&Bs[buf][n][kb]);
                bf[in][1] = *reinterpret_cast<const uint32_t*>(&Bs[buf][n][kb + 8]);
            }
#pragma unroll
            for (int im = 0; im < 4; im++)
#pragma unroll
                for (int in = 0; in < 4; in++)
                    mma_bf16(acc[im][in], af[im], bf[in]);
        }
        __syncthreads();
    }

    // ---- epilogue: bias + packed-mask + threshold append ----
    float bias2[4][2];
#pragma unroll
    for (int in = 0; in < 4; in++) {
        int gc = ib + warp_n * 32 + in * 8 + t2;
        if (gc < NI) {
            float2 bq = *reinterpret_cast<const float2*>(bias + gc);
            bias2[in][0] = bq.x; bias2[in][1] = bq.y;
        } else { bias2[in][0] = 0.f; bias2[in][1] = 0.f; }
    }
#pragma unroll
    for (int im = 0; im < 4; im++) {
#pragma unroll
        for (int half = 0; half < 2; half++) {
            const int r  = warp_m * 64 + im * 16 + g + half * 8;
            const int gr = u0 + r;
            const float th = th_s[r];
            // 4 mask bytes covering this thread's 32-col span (aligned u32)
            const uint32_t mb32 = *reinterpret_cast<const uint32_t*>(
                g_maskBits + (size_t)gr * BPR + (ib >> 3) + warp_n * 4);
#pragma unroll
            for (int in = 0; in < 4; in++) {
                const int gc = ib + warp_n * 32 + in * 8 + t2;
                const unsigned mbyte = (mb32 >> (8 * in)) & 0xffu;
                float v0 = acc[im][in][half * 2]     + bias2[in][0];
                float v1 = acc[im][in][half * 2 + 1] + bias2[in][1];
                if (!((mbyte >> t2) & 1u) && v0 >= th) {
                    int slot = atomicAdd(&g_cnt[gr], 1);
                    if (slot < CAP) g_candBuf[(size_t)gr * CAP + slot] = packCand(v0, gc);
                }
                if (!((mbyte >> (t2 + 1)) & 1u) && v1 >= th) {
                    int slot = atomicAdd(&g_cnt[gr], 1);
                    if (slot < CAP) g_candBuf[(size_t)gr * CAP + slot] = packCand(v1, gc + 1);
                }
            }
        }
    }
}

// ---- per-row top-16 over candidate buffer; mode0: write thresh, mode1: candI
__global__ void __launch_bounds__(256) kSel(int mode) {
    __shared__ float sv[256 * TOPC];
    __shared__ int   si[256 * TOPC];
    const int tid = threadIdx.x;
    const int row = blockIdx.x;
    const int n = min(g_cnt[row], CAP);
    const unsigned long long* buf = g_candBuf + (size_t)row * CAP;

    float lv[TOPC]; int li[TOPC];
#pragma unroll
    for (int j = 0; j < TOPC; j++) { lv[j] = -FLT_MAX; li[j] = 0x7fffffff; }

    for (int i = tid; i < n; i += 256) {
        float v; int idx;
        unpackCand(buf[i], v, idx);
        if (better(v, idx, lv[TOPC - 1], li[TOPC - 1])) {
            float cv = v; int ci = idx;
#pragma unroll
            for (int q = 0; q < TOPC; q++) {
                if (better(cv, ci, lv[q], li[q])) {
                    float tv = lv[q]; int ti = li[q];
                    lv[q] = cv; li[q] = ci; cv = tv; ci = ti;
                }
            }
        }
    }
#pragma unroll
    for (int j = 0; j < TOPC; j++) { sv[tid * TOPC + j] = lv[j]; si[tid * TOPC + j] = li[j]; }
    __syncthreads();

    for (int s = 128; s > 0; s >>= 1) {
        if (tid < s) {
            float av[TOPC], bv[TOPC], ov[TOPC];
            int   ai[TOPC], bi[TOPC], oi[TOPC];
#pragma unroll
            for (int j = 0; j < TOPC; j++) {
                av[j] = sv[tid * TOPC + j];       ai[j] = si[tid * TOPC + j];
                bv[j] = sv[(tid + s) * TOPC + j]; bi[j] = si[(tid + s) * TOPC + j];
            }
            int pa = 0, pb = 0;
#pragma unroll
            for (int q = 0; q < TOPC; q++) {
                bool takeA;
                if (pa >= TOPC)      takeA = false;
                else if (pb >= TOPC) takeA = true;
                else                 takeA = better(av[pa], ai[pa], bv[pb], bi[pb]);
                if (takeA) { ov[q] = av[pa]; oi[q] = ai[pa]; pa++; }
                else       { ov[q] = bv[pb]; oi[q] = bi[pb]; pb++; }
            }
#pragma unroll
            for (int j = 0; j < TOPC; j++) { sv[tid * TOPC + j] = ov[j]; si[tid * TOPC + j] = oi[j]; }
        }
        __syncthreads();
    }
    if (mode == 0) {
        if (tid == 0)
            g_thresh[row] = (n >= TOPC && sv[TOPC - 1] > -FLT_MAX)
                                ? sv[TOPC - 1] - 1e-6f : -FLT_MAX;
    } else {
        if (tid < TOPC) g_candI[(size_t)row * TOPC + tid] = si[tid];
    }
}

// ---- fp64 re-score candidates; near-tie -> lower index ----------------------
__global__ void __launch_bounds__(128) kRescore(
    const int* __restrict__ users, const float* __restrict__ embu,
    const float* __restrict__ embi, const float* __restrict__ bias,
    float* __restrict__ out) {
    const int warp = threadIdx.x >> 5;
    const int lane = threadIdx.x & 31;
    const int row  = blockIdx.x * 4 + warp;
    if (row >= NB) return;
    const int u = users[row];

    double cs[TOPC]; int ci[TOPC];
    for (int j = 0; j < TOPC; j++) {
        int idx = g_candI[(size_t)row * TOPC + j];
        ci[j] = idx;
        double s;
        if (idx < 0 || idx >= NI) {
            s = -1e300;
        } else {
            double part = 0.0;
            const float* urow = embu + (size_t)u * DIM;
            const float* irow = embi + (size_t)idx * DIM;
#pragma unroll
            for (int m = 0; m < DIM / 32; m++) {
                int k = lane + 32 * m;
                part += (double)urow[k] * (double)irow[k];
            }
#pragma unroll
            for (int off = 16; off > 0; off >>= 1)
                part += __shfl_down_sync(0xffffffffu, part, off);
            s = part + (double)bias[idx];
            s = __shfl_sync(0xffffffffu, s, 0);
        }
        cs[j] = s;
    }

    if (lane == 0) {
#pragma unroll
        for (int a = 1; a < TOPC; a++) {
            double v = cs[a]; int id = ci[a];
            int b = a - 1;
            while (b >= 0 && !beforeD(cs[b], ci[b], v, id)) {
                cs[b + 1] = cs[b]; ci[b + 1] = ci[b]; b--;
            }
            cs[b + 1] = v; ci[b + 1] = id;
        }
        for (int t = 0; t < TOPK; t++)
            out[(size_t)row * TOPK + t] = (float)ci[t];
    }
}

// ---- launch -----------------------------------------------------------------
extern "C" void kernel_launch(void* const* d_in, const int* in_sizes, int n_in,
                              void* d_out, int out_size) {
    const int*   users = nullptr;
    const float* embu  = nullptr;
    const float* embi  = nullptr;
    const float* bias  = nullptr;
    const void*  mask  = nullptr;

    for (int i = 0; i < n_in; i++) {
        long long s = in_sizes[i];
        if      (s == 4096LL      || s == 16384LL)      users = (const int*)d_in[i];
        else if (s == 4194304LL   || s == 16777216LL)   embu  = (const float*)d_in[i];
        else if (s == 12800000LL  || s == 51200000LL)   embi  = (const float*)d_in[i];
        else if (s == 50000LL     || s == 200000LL)     bias  = (const float*)d_in[i];
        else if (s == 1LL         || s == 4LL)          { /* k == 10 */ }
        else                                            mask  = d_in[i];
    }
    float* out = (float*)d_out;

    kDetectMask<<<1, 256>>>((const unsigned char*)mask);
    kInit<<<(NB + 255) / 256, 256>>>();
    kConvItems<<<(int)(((size_t)NIPAD * DIM / 8 + 255) / 256), 256>>>(embi);
    kConvUsers<<<(int)(((size_t)NB * DIM / 8 + 255) / 256), 256>>>(embu, users);
    kPackMask<<<NB, 256>>>(users, mask);
    kMainTC<<<dim3(TILES_S, NB / BM), 256>>>(bias, 0);             // seed phase
    kSel<<<NB, 256>>>(0);                                          // -> thresholds
    kMainTC<<<dim3(NTILES - TILES_S, NB / BM), 256>>>(bias, TILES_S);  // main phase
    kSel<<<NB, 256>>>(1);                                          // -> top-16
    kRescore<<<NB / 4, 128>>>(users, embu, embi, bias, out);
}